// round 16
// baseline (speedup 1.0000x reference)
#include <cuda_runtime.h>

// BurstSnn: burst encoder + 2-layer LIF SNN, 32 timesteps.
// x [B,187] f32, W1 [50,187] f32, W2 [5,50] f32
// out: spk_rec [32,B,5] f32 then counts [B] f32
//
// Encoder = 8-entry LUT on floor(8x); spikes end by t=5. Two samples/warp.
// No smem; W1t/colsums/W2 in __device__ globals (prep kernel also zeroes
// spk_rec). 128-thread blocks (2048 blocks) for fine-grained load balancing
// (block runtimes are data-dependent; no block-level coupling exists).
// Bucket-sum reuse: V0 carries t0->t1; V2 kept separate (c2) so t2 is
// bucket-7-events-only; K5/K6 captured at t3 make t4 and t5 loop-free.

#define T_STEPS 32
#define DDIM 187
#define HDIM 50
#define CDIM 5
#define NGRP 12
#define W1PAD 52          // floats per W1t row (208 B)
#define W2PAD 68
#define GSTR  3328        // 16 rows * 208 B = one group

// per-bucket spike-time masks, packed byte k = pattern(bucket k)
#define PAT_PACK 0x071B2B0B03050100ull

__device__ __align__(16) float g_w1t[DDIM * W1PAD + 16];  // [d][u] transposed
__device__ __align__(16) float g_col[64];                 // column sums
__device__ __align__(16) float g_w2[16 * W2PAD];          // padded W2 rows

__device__ __forceinline__ void addx2(unsigned long long &a, unsigned long long b) {
    asm("add.rn.f32x2 %0, %1, %2;" : "=l"(a) : "l"(a), "l"(b));
}
__device__ __forceinline__ void mulx2(unsigned long long &a, unsigned long long b) {
    asm("mul.rn.f32x2 %0, %1, %2;" : "=l"(a) : "l"(a), "l"(b));
}
__device__ __forceinline__ unsigned long long packx2(float lo, float hi) {
    unsigned long long r; asm("mov.b64 %0, {%1,%2};" : "=l"(r) : "f"(lo), "f"(hi)); return r;
}
__device__ __forceinline__ void unpackx2(unsigned long long v, float &lo, float &hi) {
    asm("mov.b64 {%0,%1}, %2;" : "=f"(lo), "=f"(hi) : "l"(v));
}

// -------- prep: transpose W1, colsums, pad W2, zero spk_rec --------
__global__ void prep_kernel(const float* __restrict__ W1,
                            const float* __restrict__ W2,
                            float* __restrict__ out, int B)
{
    const int tid = threadIdx.x;
    const int blk = blockIdx.x;
    if (blk < 38) {
        int idx = blk * 256 + tid;
        if (idx < DDIM * W1PAD) {
            int d = idx / W1PAD, u = idx - d * W1PAD;
            g_w1t[idx] = (u < HDIM) ? W1[u * DDIM + d] : 0.0f;
        }
    } else if (blk == 38) {
        if (tid < 64) {
            float sa = 0.0f, sb = 0.0f;
            if (tid < HDIM) {
                const float* row = W1 + tid * DDIM;
                int d = 0;
                for (; d + 1 < DDIM; d += 2) { sa += row[d]; sb += row[d + 1]; }
                for (; d < DDIM; d++) sa += row[d];
            }
            g_col[tid] = sa + sb;
        } else if (tid < 80) {
            g_w1t[DDIM * W1PAD + (tid - 64)] = 0.0f;
        }
    } else if (blk == 39) {
        for (int i = tid; i < 16 * W2PAD; i += 256) {
            int c = i / W2PAD, h = i - c * W2PAD;
            g_w2[i] = (c < CDIM && h < HDIM) ? W2[c * HDIM + h] : 0.0f;
        }
    } else {                              // blocks 40..143: zero spk_rec
        float4* o4 = (float4*)out;
        int n4 = (T_STEPS * B * CDIM) >> 2;
        int start = (blk - 40) * 256 + tid;
        for (int i = start; i < n4; i += 104 * 256)
            o4[i] = make_float4(0.f, 0.f, 0.f, 0.f);
    }
}

// pair-unrolled single-chain event accumulation; mask may span 2 groups
__device__ __forceinline__ void ev_accum(unsigned mh, const char* gb,
                                         unsigned long long &A01,
                                         unsigned long long &A23) {
    while (mh) {
        int i0 = __ffs(mh) - 1; mh &= mh - 1;
        const ulonglong2 w0 = *(const ulonglong2*)(gb + i0 * 208);
        if (mh) {
            int i1 = __ffs(mh) - 1; mh &= mh - 1;
            const ulonglong2 w1 = *(const ulonglong2*)(gb + i1 * 208);
            addx2(A01, w0.x); addx2(A23, w0.y);
            addx2(A01, w1.x); addx2(A23, w1.y);
        } else {
            addx2(A01, w0.x); addx2(A23, w0.y);
        }
    }
}

// layer-2 sparse gather + LIF2 + store (shared by fixed and tail steps)
__device__ __forceinline__ void l2_core(unsigned anyS1,
                                        unsigned b0, unsigned b1,
                                        unsigned b2, unsigned b3,
                                        int hl, int shamt,
                                        const float* __restrict__ w2b,
                                        float &m2, bool valid, bool &sp2,
                                        float* &po, unsigned tstride4) {
    float cur2 = 0.0f;
    if (anyS1) {
        unsigned f;
        f = (b0 >> shamt) & 0xffffu;
        while (f) { int i = __ffs(f) - 1; f &= f - 1;
                    if (hl < CDIM) cur2 += w2b[4 * i + 0]; }
        f = (b1 >> shamt) & 0xffffu;
        while (f) { int i = __ffs(f) - 1; f &= f - 1;
                    if (hl < CDIM) cur2 += w2b[4 * i + 1]; }
        f = (b2 >> shamt) & 0xffffu;
        while (f) { int i = __ffs(f) - 1; f &= f - 1;
                    if (hl < CDIM) cur2 += w2b[4 * i + 2]; }
        f = (b3 >> shamt) & 0xffffu;
        while (f) { int i = __ffs(f) - 1; f &= f - 1;
                    if (hl < CDIM) cur2 += w2b[4 * i + 3]; }
    }
    m2 = 0.9f * m2 + cur2;
    sp2 = (hl < CDIM) && (m2 > 1.0f);
    if (sp2) { m2 -= 1.0f; if (valid) *po = 1.0f; }
    po = (float*)((char*)po + tstride4);
}

// LIF1 threshold/reset + layer-2/store. Fixed steps: no quiescence ballot.
__device__ __forceinline__ void lif_fixed(unsigned long long &m01,
                                          unsigned long long &m23,
                                          bool v01, bool v23,
                                          int hl, int shamt,
                                          const float* __restrict__ w2b,
                                          float &m2, bool valid,
                                          float* &po, unsigned tstride4) {
    float a0, a1, a2, a3;
    unpackx2(m01, a0, a1); unpackx2(m23, a2, a3);
    bool s0 = v01 && (a0 > 1.0f), s1 = v01 && (a1 > 1.0f);
    bool s2 = v23 && (a2 > 1.0f), s3 = v23 && (a3 > 1.0f);
    if (s0) a0 -= 1.0f; if (s1) a1 -= 1.0f;
    if (s2) a2 -= 1.0f; if (s3) a3 -= 1.0f;
    m01 = packx2(a0, a1); m23 = packx2(a2, a3);
    unsigned b0 = __ballot_sync(0xffffffffu, s0);
    unsigned b1 = __ballot_sync(0xffffffffu, s1);
    unsigned b2 = __ballot_sync(0xffffffffu, s2);
    unsigned b3 = __ballot_sync(0xffffffffu, s3);
    bool sp2;
    l2_core(b0 | b1 | b2 | b3, b0, b1, b2, b3, hl, shamt, w2b, m2,
            valid, sp2, po, tstride4);
}

// Tail steps: also returns activity flag for the quiescence break.
__device__ __forceinline__ unsigned lif_tail(unsigned long long &m01,
                                             unsigned long long &m23,
                                             bool v01, bool v23,
                                             int hl, int shamt,
                                             const float* __restrict__ w2b,
                                             float &m2, bool valid,
                                             float* &po, unsigned tstride4) {
    float a0, a1, a2, a3;
    unpackx2(m01, a0, a1); unpackx2(m23, a2, a3);
    bool s0 = v01 && (a0 > 1.0f), s1 = v01 && (a1 > 1.0f);
    bool s2 = v23 && (a2 > 1.0f), s3 = v23 && (a3 > 1.0f);
    if (s0) a0 -= 1.0f; if (s1) a1 -= 1.0f;
    if (s2) a2 -= 1.0f; if (s3) a3 -= 1.0f;
    m01 = packx2(a0, a1); m23 = packx2(a2, a3);
    unsigned b0 = __ballot_sync(0xffffffffu, s0);
    unsigned b1 = __ballot_sync(0xffffffffu, s1);
    unsigned b2 = __ballot_sync(0xffffffffu, s2);
    unsigned b3 = __ballot_sync(0xffffffffu, s3);
    unsigned anyS1 = b0 | b1 | b2 | b3;
    bool sp2;
    l2_core(anyS1, b0, b1, b2, b3, hl, shamt, w2b, m2, valid, sp2, po, tstride4);
    unsigned anyS2 = __ballot_sync(0xffffffffu, sp2);
    return anyS1 | anyS2;
}

// packed-pattern access (j compile-time in unrolled loops)
#define PATW(j)   ((j) < 4 ? pA : ((j) < 8 ? pB : pC))
#define UNIW(j)   ((j) < 4 ? uA : ((j) < 8 ? uB : uC))
#define PBYTE(j)  ((PATW(j) >> (8 * ((j) & 3))) & 0xffu)
#define PBIT(j,t) ((PATW(j) >> (8 * ((j) & 3) + (t))) & 1u)
#define UBIT(j,t) ((UNIW(j) >> (8 * ((j) & 3) + (t))) & 1u)

#define PAIRMASK(bal0, bal1, hi_mask) \
    ((((bal0) >> shamt) & 0xffffu) | ((((bal1) >> shamt) & (hi_mask)) << 16))

__global__ __launch_bounds__(128, 12)
void burst_snn_kernel(const float* __restrict__ x,
                      float* __restrict__ out, int B)
{
    const int tid  = threadIdx.x;
    const int lane = tid & 31;
    const int hl   = lane & 15;
    const int half = lane >> 4;
    const int b    = (blockIdx.x * 4 + (tid >> 5)) * 2 + half;
    const bool valid = (b < B);

    const unsigned long long BETA2 = packx2(0.9f, 0.9f);

    // ---- encoder LUT: packed spike patterns, byte per group ----
    const float* xb = x + (size_t)b * DDIM;
    unsigned pA = 0u, pB = 0u, pC = 0u;
#pragma unroll
    for (int j = 0; j < NGRP; j++) {
        int d = hl + 16 * j;
        unsigned p = 0u;
        if (valid && d < DDIM) {
            unsigned bucket = (unsigned)(__ldg(xb + d) * 8.0f);   // exact
            p = (unsigned)((PAT_PACK >> (bucket * 8)) & 0xffu);
        }
        if (j < 4)      pA |= p << (8 * j);
        else if (j < 8) pB |= p << (8 * (j - 4));
        else            pC |= p << (8 * (j - 8));
    }
    int cnt = __popc(pA) + __popc(pB) + __popc(pC);

    const unsigned uA = __reduce_or_sync(0xffffffffu, pA);
    const unsigned uB = __reduce_or_sync(0xffffffffu, pB);
    const unsigned uC = __reduce_or_sync(0xffffffffu, pC);

    const bool v01 = (hl < 13), v23 = (hl < 12);

    unsigned long long m01, m23;
    float m2 = 0.0f;

    const char*  wb  = (const char*)g_w1t + hl * 16;
    const float* w2b = g_w2 + hl * W2PAD;
    const int shamt = lane & 16;
    float* po = out + b * CDIM + hl;
    const unsigned tstride4 = (unsigned)B * CDIM * sizeof(float);

    const ulonglong2 cs = *(const ulonglong2*)((const char*)g_col + hl * 16);
    float g0, g1, g2, g3;
    unpackx2(cs.x, g0, g1); unpackx2(cs.y, g2, g3);

    unsigned long long c01 = 0ull, c23 = 0ull;     // V0 (+V1 at t1)
    unsigned long long c2_01 = 0ull, c2_23 = 0ull; // V2 (separate, reused at t2)

    // ===== t = 0: complement (non-spikers = bucket 0) -> c = V0 =====
    {
#pragma unroll
        for (int k = 0; k < 6; k++) {
            const int j0 = 2 * k, j1 = 2 * k + 1;
            unsigned bal0 = __ballot_sync(0xffffffffu, PBIT(j0, 0) != 0u);
            unsigned bal1 = __ballot_sync(0xffffffffu, PBIT(j1, 0) != 0u);
            unsigned mh = PAIRMASK(~bal0, ~bal1, (k == 5) ? 0x07ffu : 0xffffu);
            ev_accum(mh, wb + j0 * GSTR, c01, c23);
        }
        float c0, c1, c2, c3;
        unpackx2(c01, c0, c1); unpackx2(c23, c2, c3);
        m01 = packx2(g0 - c0, g1 - c1);
        m23 = packx2(g2 - c2, g3 - c3);
        lif_fixed(m01, m23, v01, v23, hl, shamt, w2b, m2, valid, po, tstride4);
    }

    // ===== t = 1: c += V1 ; c2 = V2 ; cur = colsum - c - c2 =====
    {
        mulx2(m01, BETA2); mulx2(m23, BETA2);
#pragma unroll
        for (int k = 0; k < 6; k++) {
            const int j0 = 2 * k, j1 = 2 * k + 1;
            unsigned bal0 = __ballot_sync(0xffffffffu, PBYTE(j0) == 0x01u);
            unsigned bal1 = __ballot_sync(0xffffffffu, PBYTE(j1) == 0x01u);
            unsigned mh = PAIRMASK(bal0, bal1, 0xffffu);
            ev_accum(mh, wb + j0 * GSTR, c01, c23);           // bucket 1
            unsigned bb0 = __ballot_sync(0xffffffffu, PBYTE(j0) == 0x05u);
            unsigned bb1 = __ballot_sync(0xffffffffu, PBYTE(j1) == 0x05u);
            unsigned mh2 = PAIRMASK(bb0, bb1, 0xffffu);
            ev_accum(mh2, wb + j0 * GSTR, c2_01, c2_23);      // bucket 2
        }
        float a0, a1, a2, a3, c0, c1, c2, c3, d0, d1, d2, d3;
        unpackx2(m01, a0, a1); unpackx2(m23, a2, a3);
        unpackx2(c01, c0, c1); unpackx2(c23, c2, c3);
        unpackx2(c2_01, d0, d1); unpackx2(c2_23, d2, d3);
        a0 += g0 - c0 - d0; a1 += g1 - c1 - d1;
        a2 += g2 - c2 - d2; a3 += g3 - c3 - d3;
        m01 = packx2(a0, a1); m23 = packx2(a2, a3);
        lif_fixed(m01, m23, v01, v23, hl, shamt, w2b, m2, valid, po, tstride4);
    }

    // ===== t = 2: cur = V2 (c2) + bucket-7 events =====
    {
        mulx2(m01, BETA2); mulx2(m23, BETA2);
        addx2(m01, c2_01); addx2(m23, c2_23);
#pragma unroll
        for (int k = 0; k < 6; k++) {
            const int j0 = 2 * k, j1 = 2 * k + 1;
            if (!UBIT(j0, 2) && !UBIT(j1, 2)) continue;
            unsigned bal0 = __ballot_sync(0xffffffffu, PBYTE(j0) == 0x07u);
            unsigned bal1 = __ballot_sync(0xffffffffu, PBYTE(j1) == 0x07u);
            unsigned mh = PAIRMASK(bal0, bal1, 0xffffu);
            ev_accum(mh, wb + j0 * GSTR, m01, m23);
        }
        lif_fixed(m01, m23, v01, v23, hl, shamt, w2b, m2, valid, po, tstride4);
    }

    // ===== t = 3: bucket4 -> m ; bucket6 -> K6 ; bucket5 -> K5 =====
    unsigned long long k6_01 = 0ull, k6_23 = 0ull;
    unsigned long long k5_01 = 0ull, k5_23 = 0ull;
    {
        mulx2(m01, BETA2); mulx2(m23, BETA2);
#pragma unroll
        for (int k = 0; k < 6; k++) {
            const int j0 = 2 * k, j1 = 2 * k + 1;
            if (UBIT(j0, 3) || UBIT(j1, 3)) {   // any bucket in {4,5,6}
                unsigned bal0 = __ballot_sync(0xffffffffu,
                                              ((PBYTE(j0) >> 3) & 7u) == 1u);
                unsigned bal1 = __ballot_sync(0xffffffffu,
                                              ((PBYTE(j1) >> 3) & 7u) == 1u);
                unsigned mh = PAIRMASK(bal0, bal1, 0xffffu);
                ev_accum(mh, wb + j0 * GSTR, m01, m23);       // bucket 4
            }
            if (UBIT(j0, 4) || UBIT(j1, 4)) {
                unsigned bal0 = __ballot_sync(0xffffffffu, PBIT(j0, 4) != 0u);
                unsigned bal1 = __ballot_sync(0xffffffffu, PBIT(j1, 4) != 0u);
                unsigned mh = PAIRMASK(bal0, bal1, 0xffffu);
                ev_accum(mh, wb + j0 * GSTR, k6_01, k6_23);   // bucket 6
            }
            if (UBIT(j0, 5) || UBIT(j1, 5)) {
                unsigned bal0 = __ballot_sync(0xffffffffu, PBIT(j0, 5) != 0u);
                unsigned bal1 = __ballot_sync(0xffffffffu, PBIT(j1, 5) != 0u);
                unsigned mh = PAIRMASK(bal0, bal1, 0xffffu);
                ev_accum(mh, wb + j0 * GSTR, k5_01, k5_23);   // bucket 5
            }
        }
        addx2(m01, k5_01); addx2(m23, k5_23);
        addx2(m01, k6_01); addx2(m23, k6_23);
        lif_fixed(m01, m23, v01, v23, hl, shamt, w2b, m2, valid, po, tstride4);
    }

    // ===== t = 4: cur = K6 (loop-free) =====
    {
        mulx2(m01, BETA2); mulx2(m23, BETA2);
        addx2(m01, k6_01); addx2(m23, k6_23);
        lif_fixed(m01, m23, v01, v23, hl, shamt, w2b, m2, valid, po, tstride4);
    }

    // ===== t = 5: cur = K5 (loop-free) =====
    {
        mulx2(m01, BETA2); mulx2(m23, BETA2);
        addx2(m01, k5_01); addx2(m23, k5_23);
        lif_fixed(m01, m23, v01, v23, hl, shamt, w2b, m2, valid, po, tstride4);
    }

    // ===== tail t >= 6: encoder silent, LIF decay only =====
#pragma unroll 1
    for (int t = 6; t < T_STEPS; t++) {
        mulx2(m01, BETA2); mulx2(m23, BETA2);
        unsigned any = lif_tail(m01, m23, v01, v23, hl, shamt, w2b, m2,
                                valid, po, tstride4);
        if (any == 0u) break;    // membranes <= 1, only decay: all zero ahead
    }

    // ---- spike counts (closed form; reduce within 16-lane half) ----
#pragma unroll
    for (int off = 8; off; off >>= 1)
        cnt += __shfl_xor_sync(0xffffffffu, cnt, off);
    if (valid && hl == 0)
        out[(size_t)T_STEPS * B * CDIM + b] = (float)cnt;
}

extern "C" void kernel_launch(void* const* d_in, const int* in_sizes, int n_in,
                              void* d_out, int out_size)
{
    const float* x  = (const float*)d_in[0];
    const float* W1 = (const float*)d_in[1];
    const float* W2 = (const float*)d_in[2];
    float* out = (float*)d_out;

    int B = in_sizes[0] / DDIM;
    prep_kernel<<<144, 256>>>(W1, W2, out, B);   // transpose + colsum + zero
    int blocks = (B + 7) / 8;    // 4 warps/block, 2 samples/warp
    burst_snn_kernel<<<blocks, 128>>>(x, out, B);
}

// round 17
// speedup vs baseline: 1.0742x; 1.0742x over previous
#include <cuda_runtime.h>

// BurstSnn: burst encoder + 2-layer LIF SNN, 32 timesteps.
// x [B,187] f32, W1 [50,187] f32, W2 [5,50] f32
// out: spk_rec [32,B,5] f32 then counts [B] f32
//
// Encoder = 8-entry LUT on floor(8x); spikes end by t=5. Two samples/warp.
// No smem: W1t/colsums/W2 in __device__ globals (prep kernel also zeroes
// spk_rec). 256-thread blocks, launch_bounds(256,8): ptxas already needs only
// 32 regs, so the tighter cap raises residency 7->8 blocks/SM (64 warps).
// Event loops process GROUP PAIRS with one 32-bit mask. Bucket-sum reuse:
// V0 carries t0->t1; K5/K6 captured at t3 make t4 AND t5 loop-free.

#define T_STEPS 32
#define DDIM 187
#define HDIM 50
#define CDIM 5
#define NGRP 12
#define W1PAD 52          // floats per W1t row (208 B)
#define W2PAD 68
#define GSTR  3328        // 16 rows * 208 B = one group

// per-bucket spike-time masks, packed byte k = pattern(bucket k)
#define PAT_PACK 0x071B2B0B03050100ull

__device__ __align__(16) float g_w1t[DDIM * W1PAD + 16];  // [d][u] transposed
__device__ __align__(16) float g_col[64];                 // column sums
__device__ __align__(16) float g_w2[16 * W2PAD];          // padded W2 rows

__device__ __forceinline__ void addx2(unsigned long long &a, unsigned long long b) {
    asm("add.rn.f32x2 %0, %1, %2;" : "=l"(a) : "l"(a), "l"(b));
}
__device__ __forceinline__ void mulx2(unsigned long long &a, unsigned long long b) {
    asm("mul.rn.f32x2 %0, %1, %2;" : "=l"(a) : "l"(a), "l"(b));
}
__device__ __forceinline__ unsigned long long packx2(float lo, float hi) {
    unsigned long long r; asm("mov.b64 %0, {%1,%2};" : "=l"(r) : "f"(lo), "f"(hi)); return r;
}
__device__ __forceinline__ void unpackx2(unsigned long long v, float &lo, float &hi) {
    asm("mov.b64 {%0,%1}, %2;" : "=f"(lo), "=f"(hi) : "l"(v));
}

// -------- prep: transpose W1, colsums, pad W2, zero spk_rec --------
__global__ void prep_kernel(const float* __restrict__ W1,
                            const float* __restrict__ W2,
                            float* __restrict__ out, int B)
{
    const int tid = threadIdx.x;
    const int blk = blockIdx.x;
    if (blk < 38) {
        int idx = blk * 256 + tid;
        if (idx < DDIM * W1PAD) {
            int d = idx / W1PAD, u = idx - d * W1PAD;
            g_w1t[idx] = (u < HDIM) ? W1[u * DDIM + d] : 0.0f;
        }
    } else if (blk == 38) {
        if (tid < 64) {
            float sa = 0.0f, sb = 0.0f;
            if (tid < HDIM) {
                const float* row = W1 + tid * DDIM;
                int d = 0;
                for (; d + 1 < DDIM; d += 2) { sa += row[d]; sb += row[d + 1]; }
                for (; d < DDIM; d++) sa += row[d];
            }
            g_col[tid] = sa + sb;
        } else if (tid < 80) {
            g_w1t[DDIM * W1PAD + (tid - 64)] = 0.0f;
        }
    } else if (blk == 39) {
        for (int i = tid; i < 16 * W2PAD; i += 256) {
            int c = i / W2PAD, h = i - c * W2PAD;
            g_w2[i] = (c < CDIM && h < HDIM) ? W2[c * HDIM + h] : 0.0f;
        }
    } else {                              // blocks 40..143: zero spk_rec
        float4* o4 = (float4*)out;
        int n4 = (T_STEPS * B * CDIM) >> 2;
        int start = (blk - 40) * 256 + tid;
        for (int i = start; i < n4; i += 104 * 256)
            o4[i] = make_float4(0.f, 0.f, 0.f, 0.f);
    }
}

// pair-unrolled single-chain event accumulation; mask may span 2 groups
// (addresses are linear in bit index: gb + bit*208)
__device__ __forceinline__ void ev_accum(unsigned mh, const char* gb,
                                         unsigned long long &A01,
                                         unsigned long long &A23) {
    while (mh) {
        int i0 = __ffs(mh) - 1; mh &= mh - 1;
        const ulonglong2 w0 = *(const ulonglong2*)(gb + i0 * 208);
        if (mh) {
            int i1 = __ffs(mh) - 1; mh &= mh - 1;
            const ulonglong2 w1 = *(const ulonglong2*)(gb + i1 * 208);
            addx2(A01, w0.x); addx2(A23, w0.y);
            addx2(A01, w1.x); addx2(A23, w1.y);
        } else {
            addx2(A01, w0.x); addx2(A23, w0.y);
        }
    }
}

// layer-2 sparse gather + LIF2 + store (shared by fixed and tail steps)
__device__ __forceinline__ void l2_core(unsigned anyS1,
                                        unsigned b0, unsigned b1,
                                        unsigned b2, unsigned b3,
                                        int hl, int shamt,
                                        const float* __restrict__ w2b,
                                        float &m2, bool valid, bool &sp2,
                                        float* &po, unsigned tstride4) {
    float cur2 = 0.0f;
    if (anyS1) {
        unsigned f;
        f = (b0 >> shamt) & 0xffffu;
        while (f) { int i = __ffs(f) - 1; f &= f - 1;
                    if (hl < CDIM) cur2 += w2b[4 * i + 0]; }
        f = (b1 >> shamt) & 0xffffu;
        while (f) { int i = __ffs(f) - 1; f &= f - 1;
                    if (hl < CDIM) cur2 += w2b[4 * i + 1]; }
        f = (b2 >> shamt) & 0xffffu;
        while (f) { int i = __ffs(f) - 1; f &= f - 1;
                    if (hl < CDIM) cur2 += w2b[4 * i + 2]; }
        f = (b3 >> shamt) & 0xffffu;
        while (f) { int i = __ffs(f) - 1; f &= f - 1;
                    if (hl < CDIM) cur2 += w2b[4 * i + 3]; }
    }
    m2 = 0.9f * m2 + cur2;
    sp2 = (hl < CDIM) && (m2 > 1.0f);
    if (sp2) { m2 -= 1.0f; if (valid) *po = 1.0f; }
    po = (float*)((char*)po + tstride4);
}

// LIF1 threshold/reset + layer-2/store. Fixed steps: no quiescence ballot.
__device__ __forceinline__ void lif_fixed(unsigned long long &m01,
                                          unsigned long long &m23,
                                          bool v01, bool v23,
                                          int hl, int shamt,
                                          const float* __restrict__ w2b,
                                          float &m2, bool valid,
                                          float* &po, unsigned tstride4) {
    float a0, a1, a2, a3;
    unpackx2(m01, a0, a1); unpackx2(m23, a2, a3);
    bool s0 = v01 && (a0 > 1.0f), s1 = v01 && (a1 > 1.0f);
    bool s2 = v23 && (a2 > 1.0f), s3 = v23 && (a3 > 1.0f);
    if (s0) a0 -= 1.0f; if (s1) a1 -= 1.0f;
    if (s2) a2 -= 1.0f; if (s3) a3 -= 1.0f;
    m01 = packx2(a0, a1); m23 = packx2(a2, a3);
    unsigned b0 = __ballot_sync(0xffffffffu, s0);
    unsigned b1 = __ballot_sync(0xffffffffu, s1);
    unsigned b2 = __ballot_sync(0xffffffffu, s2);
    unsigned b3 = __ballot_sync(0xffffffffu, s3);
    bool sp2;
    l2_core(b0 | b1 | b2 | b3, b0, b1, b2, b3, hl, shamt, w2b, m2,
            valid, sp2, po, tstride4);
}

// Tail steps: also returns activity flag for the quiescence break.
__device__ __forceinline__ unsigned lif_tail(unsigned long long &m01,
                                             unsigned long long &m23,
                                             bool v01, bool v23,
                                             int hl, int shamt,
                                             const float* __restrict__ w2b,
                                             float &m2, bool valid,
                                             float* &po, unsigned tstride4) {
    float a0, a1, a2, a3;
    unpackx2(m01, a0, a1); unpackx2(m23, a2, a3);
    bool s0 = v01 && (a0 > 1.0f), s1 = v01 && (a1 > 1.0f);
    bool s2 = v23 && (a2 > 1.0f), s3 = v23 && (a3 > 1.0f);
    if (s0) a0 -= 1.0f; if (s1) a1 -= 1.0f;
    if (s2) a2 -= 1.0f; if (s3) a3 -= 1.0f;
    m01 = packx2(a0, a1); m23 = packx2(a2, a3);
    unsigned b0 = __ballot_sync(0xffffffffu, s0);
    unsigned b1 = __ballot_sync(0xffffffffu, s1);
    unsigned b2 = __ballot_sync(0xffffffffu, s2);
    unsigned b3 = __ballot_sync(0xffffffffu, s3);
    unsigned anyS1 = b0 | b1 | b2 | b3;
    bool sp2;
    l2_core(anyS1, b0, b1, b2, b3, hl, shamt, w2b, m2, valid, sp2, po, tstride4);
    unsigned anyS2 = __ballot_sync(0xffffffffu, sp2);
    return anyS1 | anyS2;
}

// packed-pattern access (j compile-time in unrolled loops)
#define PATW(j)   ((j) < 4 ? pA : ((j) < 8 ? pB : pC))
#define UNIW(j)   ((j) < 4 ? uA : ((j) < 8 ? uB : uC))
#define PBYTE(j)  ((PATW(j) >> (8 * ((j) & 3))) & 0xffu)
#define PBIT(j,t) ((PATW(j) >> (8 * ((j) & 3) + (t))) & 1u)
#define UBIT(j,t) ((UNIW(j) >> (8 * ((j) & 3) + (t))) & 1u)

// combine two per-half 16-bit masks into one 32-bit pair mask
#define PAIRMASK(bal0, bal1, hi_mask) \
    ((((bal0) >> shamt) & 0xffffu) | ((((bal1) >> shamt) & (hi_mask)) << 16))

__global__ __launch_bounds__(256, 8)
void burst_snn_kernel(const float* __restrict__ x,
                      float* __restrict__ out, int B)
{
    const int tid  = threadIdx.x;
    const int lane = tid & 31;
    const int hl   = lane & 15;
    const int half = lane >> 4;
    const int b    = (blockIdx.x * 8 + (tid >> 5)) * 2 + half;
    const bool valid = (b < B);

    const unsigned long long BETA2 = packx2(0.9f, 0.9f);

    // ---- encoder LUT: packed spike patterns, byte per group ----
    const float* xb = x + (size_t)b * DDIM;
    unsigned pA = 0u, pB = 0u, pC = 0u;
#pragma unroll
    for (int j = 0; j < NGRP; j++) {
        int d = hl + 16 * j;
        unsigned p = 0u;
        if (valid && d < DDIM) {
            unsigned bucket = (unsigned)(__ldg(xb + d) * 8.0f);   // exact
            p = (unsigned)((PAT_PACK >> (bucket * 8)) & 0xffu);
        }
        if (j < 4)      pA |= p << (8 * j);
        else if (j < 8) pB |= p << (8 * (j - 4));
        else            pC |= p << (8 * (j - 8));
    }
    int cnt = __popc(pA) + __popc(pB) + __popc(pC);

    const unsigned uA = __reduce_or_sync(0xffffffffu, pA);
    const unsigned uB = __reduce_or_sync(0xffffffffu, pB);
    const unsigned uC = __reduce_or_sync(0xffffffffu, pC);

    const bool v01 = (hl < 13), v23 = (hl < 12);

    unsigned long long m01, m23;
    float m2 = 0.0f;

    const char*  wb  = (const char*)g_w1t + hl * 16;
    const float* w2b = g_w2 + hl * W2PAD;
    const int shamt = lane & 16;
    float* po = out + b * CDIM + hl;
    const unsigned tstride4 = (unsigned)B * CDIM * sizeof(float);

    const ulonglong2 cs = *(const ulonglong2*)((const char*)g_col + hl * 16);
    float g0, g1, g2, g3;
    unpackx2(cs.x, g0, g1); unpackx2(cs.y, g2, g3);

    unsigned long long c01 = 0ull, c23 = 0ull;   // bucket-sum accumulator

    // ===== t = 0: complement (non-spikers = bucket 0) -> c = V0 =====
    {
#pragma unroll
        for (int k = 0; k < 6; k++) {
            const int j0 = 2 * k, j1 = 2 * k + 1;
            unsigned bal0 = __ballot_sync(0xffffffffu, PBIT(j0, 0) != 0u);
            unsigned bal1 = __ballot_sync(0xffffffffu, PBIT(j1, 0) != 0u);
            unsigned mh = PAIRMASK(~bal0, ~bal1, (k == 5) ? 0x07ffu : 0xffffu);
            ev_accum(mh, wb + j0 * GSTR, c01, c23);
        }
        float c0, c1, c2, c3;
        unpackx2(c01, c0, c1); unpackx2(c23, c2, c3);
        m01 = packx2(g0 - c0, g1 - c1);
        m23 = packx2(g2 - c2, g3 - c3);
        lif_fixed(m01, m23, v01, v23, hl, shamt, w2b, m2, valid, po, tstride4);
    }

    // ===== t = 1: c continues (add buckets {1,2}); cur = colsum - c =====
    {
        mulx2(m01, BETA2); mulx2(m23, BETA2);
#pragma unroll
        for (int k = 0; k < 6; k++) {
            const int j0 = 2 * k, j1 = 2 * k + 1;
            unsigned bal0 = __ballot_sync(0xffffffffu, (PBYTE(j0) & 3u) == 1u);
            unsigned bal1 = __ballot_sync(0xffffffffu, (PBYTE(j1) & 3u) == 1u);
            unsigned mh = PAIRMASK(bal0, bal1, 0xffffu);
            ev_accum(mh, wb + j0 * GSTR, c01, c23);
        }
        float a0, a1, a2, a3, c0, c1, c2, c3;
        unpackx2(m01, a0, a1); unpackx2(m23, a2, a3);
        unpackx2(c01, c0, c1); unpackx2(c23, c2, c3);
        a0 += g0 - c0; a1 += g1 - c1; a2 += g2 - c2; a3 += g3 - c3;
        m01 = packx2(a0, a1); m23 = packx2(a2, a3);
        lif_fixed(m01, m23, v01, v23, hl, shamt, w2b, m2, valid, po, tstride4);
    }

    // ===== t = 2: sparse events (buckets {2,7} = pattern bit 2) =====
    {
        mulx2(m01, BETA2); mulx2(m23, BETA2);
#pragma unroll
        for (int k = 0; k < 6; k++) {
            const int j0 = 2 * k, j1 = 2 * k + 1;
            if (!UBIT(j0, 2) && !UBIT(j1, 2)) continue;
            unsigned bal0 = __ballot_sync(0xffffffffu, PBIT(j0, 2) != 0u);
            unsigned bal1 = __ballot_sync(0xffffffffu, PBIT(j1, 2) != 0u);
            unsigned mh = PAIRMASK(bal0, bal1, 0xffffu);
            ev_accum(mh, wb + j0 * GSTR, m01, m23);
        }
        lif_fixed(m01, m23, v01, v23, hl, shamt, w2b, m2, valid, po, tstride4);
    }

    // ===== t = 3: bucket4 -> m ; bucket6 -> K6 ; bucket5 -> K5 =====
    unsigned long long k6_01 = 0ull, k6_23 = 0ull;
    unsigned long long k5_01 = 0ull, k5_23 = 0ull;
    {
        mulx2(m01, BETA2); mulx2(m23, BETA2);
#pragma unroll
        for (int k = 0; k < 6; k++) {
            const int j0 = 2 * k, j1 = 2 * k + 1;
            if (UBIT(j0, 3) || UBIT(j1, 3)) {   // any bucket in {4,5,6}
                unsigned bal0 = __ballot_sync(0xffffffffu,
                                              ((PBYTE(j0) >> 3) & 7u) == 1u);
                unsigned bal1 = __ballot_sync(0xffffffffu,
                                              ((PBYTE(j1) >> 3) & 7u) == 1u);
                unsigned mh = PAIRMASK(bal0, bal1, 0xffffu);
                ev_accum(mh, wb + j0 * GSTR, m01, m23);       // bucket 4
            }
            if (UBIT(j0, 4) || UBIT(j1, 4)) {
                unsigned bal0 = __ballot_sync(0xffffffffu, PBIT(j0, 4) != 0u);
                unsigned bal1 = __ballot_sync(0xffffffffu, PBIT(j1, 4) != 0u);
                unsigned mh = PAIRMASK(bal0, bal1, 0xffffu);
                ev_accum(mh, wb + j0 * GSTR, k6_01, k6_23);   // bucket 6
            }
            if (UBIT(j0, 5) || UBIT(j1, 5)) {
                unsigned bal0 = __ballot_sync(0xffffffffu, PBIT(j0, 5) != 0u);
                unsigned bal1 = __ballot_sync(0xffffffffu, PBIT(j1, 5) != 0u);
                unsigned mh = PAIRMASK(bal0, bal1, 0xffffu);
                ev_accum(mh, wb + j0 * GSTR, k5_01, k5_23);   // bucket 5
            }
        }
        addx2(m01, k5_01); addx2(m23, k5_23);
        addx2(m01, k6_01); addx2(m23, k6_23);
        lif_fixed(m01, m23, v01, v23, hl, shamt, w2b, m2, valid, po, tstride4);
    }

    // ===== t = 4: cur = K6 (loop-free) =====
    {
        mulx2(m01, BETA2); mulx2(m23, BETA2);
        addx2(m01, k6_01); addx2(m23, k6_23);
        lif_fixed(m01, m23, v01, v23, hl, shamt, w2b, m2, valid, po, tstride4);
    }

    // ===== t = 5: cur = K5 (loop-free) =====
    {
        mulx2(m01, BETA2); mulx2(m23, BETA2);
        addx2(m01, k5_01); addx2(m23, k5_23);
        lif_fixed(m01, m23, v01, v23, hl, shamt, w2b, m2, valid, po, tstride4);
    }

    // ===== tail t >= 6: encoder silent, LIF decay only =====
#pragma unroll 1
    for (int t = 6; t < T_STEPS; t++) {
        mulx2(m01, BETA2); mulx2(m23, BETA2);
        unsigned any = lif_tail(m01, m23, v01, v23, hl, shamt, w2b, m2,
                                valid, po, tstride4);
        if (any == 0u) break;    // membranes <= 1, only decay: all zero ahead
    }

    // ---- spike counts (closed form; reduce within 16-lane half) ----
#pragma unroll
    for (int off = 8; off; off >>= 1)
        cnt += __shfl_xor_sync(0xffffffffu, cnt, off);
    if (valid && hl == 0)
        out[(size_t)T_STEPS * B * CDIM + b] = (float)cnt;
}

extern "C" void kernel_launch(void* const* d_in, const int* in_sizes, int n_in,
                              void* d_out, int out_size)
{
    const float* x  = (const float*)d_in[0];
    const float* W1 = (const float*)d_in[1];
    const float* W2 = (const float*)d_in[2];
    float* out = (float*)d_out;

    int B = in_sizes[0] / DDIM;
    prep_kernel<<<144, 256>>>(W1, W2, out, B);   // transpose + colsum + zero
    int blocks = (B + 15) / 16;   // 8 warps/block, 2 samples/warp
    burst_snn_kernel<<<blocks, 256>>>(x, out, B);
}